// round 8
// baseline (speedup 1.0000x reference)
#include <cuda_runtime.h>
#include <cuda_bf16.h>
#include <cstdint>

// Fixed shapes for HRTExtractor_81320910782627
#define N_DOCS 4
#define LSEQ   1024
#define DMODEL 768
#define NHEAD  12
#define NE     32
#define NM     4
#define NR     256
#define POS_OFFSET 1
#define NEG_INF (-3.402823466e38f)

#define LC      32      // l-chunk for k_htA
#define NLC     (LSEQ / LC)   // 32 chunks? no: 1024/32 = 32 -> careful
// NOTE: NLC = 32 chunks of 32. grid uses NLC.

// Scratch (device globals; allocation forbidden)
__device__ float g_eemb[N_DOCS * NE * DMODEL];            // (i,e,d)
__device__ float g_eatt[N_DOCS * NE * NHEAD * LSEQ];      // (i,e,h,l)
__device__ float g_v   [N_DOCS * NR * LSEQ];              // unnormalized ht_att
__device__ float g_spart[N_DOCS * NR * NLC];              // per-chunk partial sums

// ---------------------------------------------------------------------------
// helpers: bf16 split + pack
// ---------------------------------------------------------------------------
__device__ __forceinline__ void bsplit(float x, float& hi, float& lo) {
    __nv_bfloat16 h = __float2bfloat16(x);
    float hf = __bfloat162float(h);
    hi = hf;
    lo = x - hf;
}
__device__ __forceinline__ unsigned pack2(float a, float b) {
    __nv_bfloat162 v = __floats2bfloat162_rn(a, b);
    return *reinterpret_cast<unsigned*>(&v);
}

// ---------------------------------------------------------------------------
// Kernel 1 (fused): blocks [0, 4*32*6) -> e_att (2 heads per block, MLP=8),
//                   blocks [.., +128)  -> e_emb
// ---------------------------------------------------------------------------
#define NHP (NHEAD / 2)   // 6 head-pairs

__global__ __launch_bounds__(256) void k_prep(
    const float* __restrict__ seq,      // (n, L, d)
    const float* __restrict__ att,      // (n, h, L, L)
    const int*   __restrict__ mpos,     // (n, E, M)
    const float* __restrict__ mmask)    // (n, E, M)
{
    if (blockIdx.x < N_DOCS * NE * NHP) {
        // ---- e_att: 2 heads per block ----
        int b  = blockIdx.x;
        int hp = b % NHP;
        int ie = b / NHP;
        int i  = ie / NE;
        int h0 = hp * 2;

        int   p[NM];
        float mk[NM];
        float cnt = 0.f;
        #pragma unroll
        for (int m = 0; m < NM; m++) {
            p[m]  = mpos[ie * NM + m] + POS_OFFSET;
            mk[m] = mmask[ie * NM + m];
            cnt += mk[m];
        }
        float inv = 1.f / fmaxf(cnt, 1.f);

        int l4 = threadIdx.x * 4;
        float4 a0 = make_float4(0.f, 0.f, 0.f, 0.f);
        float4 a1 = make_float4(0.f, 0.f, 0.f, 0.f);
        #pragma unroll
        for (int m = 0; m < NM; m++) {
            const float4 x = *(const float4*)&att[
                (((size_t)i * NHEAD + h0)     * LSEQ + p[m]) * LSEQ + l4];
            const float4 y = *(const float4*)&att[
                (((size_t)i * NHEAD + h0 + 1) * LSEQ + p[m]) * LSEQ + l4];
            a0.x += mk[m] * x.x; a0.y += mk[m] * x.y;
            a0.z += mk[m] * x.z; a0.w += mk[m] * x.w;
            a1.x += mk[m] * y.x; a1.y += mk[m] * y.y;
            a1.z += mk[m] * y.z; a1.w += mk[m] * y.w;
        }
        float4 o0 = make_float4(a0.x * inv, a0.y * inv, a0.z * inv, a0.w * inv);
        float4 o1 = make_float4(a1.x * inv, a1.y * inv, a1.z * inv, a1.w * inv);
        *(float4*)&g_eatt[((size_t)ie * NHEAD + h0)     * LSEQ + l4] = o0;
        *(float4*)&g_eatt[((size_t)ie * NHEAD + h0 + 1) * LSEQ + l4] = o1;
    } else {
        // ---- e_emb (logsumexp over M) ----
        int ie = blockIdx.x - N_DOCS * NE * NHP;
        int i  = ie / NE;

        __shared__ int   sp[NM];
        __shared__ float sm[NM];
        if (threadIdx.x < NM) {
            sp[threadIdx.x] = mpos[ie * NM + threadIdx.x] + POS_OFFSET;
            sm[threadIdx.x] = mmask[ie * NM + threadIdx.x];
        }
        __syncthreads();

        for (int dd = threadIdx.x; dd < DMODEL; dd += blockDim.x) {
            float v[NM];
            float mx = NEG_INF;
            #pragma unroll
            for (int m = 0; m < NM; m++) {
                float x = (sm[m] > 0.f)
                    ? seq[((size_t)i * LSEQ + sp[m]) * DMODEL + dd]
                    : NEG_INF;
                v[m] = x;
                mx = fmaxf(mx, x);
            }
            float s = 0.f;
            #pragma unroll
            for (int m = 0; m < NM; m++) s += expf(v[m] - mx);
            g_eemb[(size_t)ie * DMODEL + dd] = logf(s) + mx;
        }
    }
}

// ---------------------------------------------------------------------------
// Kernel 2: k_htA — smem-tiled pairwise head dot.
// grid (NLC=32, N_DOCS=4, 2 pair-halves). Block loads e_att[i,:,:,lchunk]
// (12*32*32 f32 = 48KB) once; warp w handles 16 pairs, lane = l within chunk.
// Writes g_v (unnormalized, incl. /NHEAD) and per-chunk sums to g_spart.
// ---------------------------------------------------------------------------
__global__ __launch_bounds__(256) void k_htA(const int* __restrict__ hts)
{
    __shared__ __align__(16) float sA[NHEAD][NE][LC];   // 48 KB

    const int lc = blockIdx.x;          // 0..31
    const int i  = blockIdx.y;          // doc
    const int rh = blockIdx.z;          // pair half
    const int l0 = lc * LC;

    // Load slice: 12*32*32 floats = 3072 float4
    for (int idx = threadIdx.x; idx < NHEAD * NE * (LC / 4); idx += 256) {
        int q  = idx & (LC / 4 - 1);        // 0..7
        int eh = idx >> 3;
        int e  = eh & (NE - 1);
        int h  = eh >> 5;
        float4 v = *(const float4*)&g_eatt[
            ((size_t)(i * NE + e) * NHEAD + h) * LSEQ + l0 + q * 4];
        *(float4*)&sA[h][e][q * 4] = v;
    }
    __syncthreads();

    const int warp = threadIdx.x >> 5;
    const int lane = threadIdx.x & 31;
    const int rbase = rh * 128 + warp * 16;

    // pairs for this warp (lanes 0..15 hold them)
    int2 ep = ((const int2*)hts)[i * NR + rbase + (lane & 15)];

    float* vout = g_v + ((size_t)i * NR + rbase) * LSEQ + l0;

    #pragma unroll 4
    for (int rr = 0; rr < 16; rr++) {
        int e0 = __shfl_sync(0xffffffffu, ep.x, rr);
        int e1 = __shfl_sync(0xffffffffu, ep.y, rr);
        float acc = 0.f;
        #pragma unroll
        for (int h = 0; h < NHEAD; h++)
            acc += sA[h][e0][lane] * sA[h][e1][lane];
        acc *= (1.f / NHEAD);
        vout[(size_t)rr * LSEQ + lane] = acc;

        float t = acc;
        #pragma unroll
        for (int o = 16; o; o >>= 1) t += __shfl_xor_sync(0xffffffffu, t, o);
        if (lane == 0)
            g_spart[(size_t)(i * NR + rbase + rr) * NLC + lc] = t;
    }
}

// ---------------------------------------------------------------------------
// Kernel 3: rs[i] = ht[i] (256 x 1024) @ seq[i] (1024 x 768) via HMMA bf16,
// 3-term split. Normalization (scale = 1/(sum+1e-5)) fused into A load path;
// hs/ts gather fused into prologue.
// Block 256 thr, BM=128 BN=64 BK=32, grid (12,2,4) = 96 blocks.
// ---------------------------------------------------------------------------
#define BM 128
#define BN 64
#define BK 32
#define AS_STRIDE 20
#define BS_STRIDE 20

__device__ __forceinline__ void mma16816(
    float& c0, float& c1, float& c2, float& c3,
    unsigned a0, unsigned a1, unsigned a2, unsigned a3,
    unsigned b0, unsigned b1)
{
    asm volatile(
        "mma.sync.aligned.m16n8k16.row.col.f32.bf16.bf16.f32 "
        "{%0,%1,%2,%3}, {%4,%5,%6,%7}, {%8,%9}, {%0,%1,%2,%3};\n"
        : "+f"(c0), "+f"(c1), "+f"(c2), "+f"(c3)
        : "r"(a0), "r"(a1), "r"(a2), "r"(a3), "r"(b0), "r"(b1));
}

__global__ __launch_bounds__(256) void k_gemm(
    const float* __restrict__ seq,      // (n, L, d)
    const int*   __restrict__ hts,
    float* __restrict__ out)
{
    __shared__ __align__(16) unsigned As_hi[BM * AS_STRIDE];
    __shared__ __align__(16) unsigned As_lo[BM * AS_STRIDE];
    __shared__ __align__(16) unsigned Bs_hi[BN * BS_STRIDE];
    __shared__ __align__(16) unsigned Bs_lo[BN * BS_STRIDE];

    const int i       = blockIdx.z;
    const int rowBase = blockIdx.y * BM;
    const int colBase = blockIdx.x * BN;

    const int tid  = threadIdx.x;
    const int wid  = tid >> 5;
    const int lane = tid & 31;
    const int g    = lane >> 2;
    const int q    = lane & 3;

    const int warp_m = (wid & 3) * 32;
    const int warp_n = (wid >> 2) * 32;

    // ---- fused hs/ts gather for this (row,col) tile ----
    {
        int row  = tid >> 1;            // 0..127
        int half = tid & 1;
        int b = i * NR + rowBase + row;
        int e0 = hts[b * 2 + 0];
        int e1 = hts[b * 2 + 1];
        const float4* eh = (const float4*)&g_eemb[
            (size_t)(i * NE + e0) * DMODEL + colBase + half * 32];
        const float4* et = (const float4*)&g_eemb[
            (size_t)(i * NE + e1) * DMODEL + colBase + half * 32];
        float4* o0 = (float4*)&out[(size_t)b * DMODEL + colBase + half * 32];
        float4* o1 = (float4*)&out[
            ((size_t)N_DOCS * NR + b) * DMODEL + colBase + half * 32];
        #pragma unroll
        for (int j = 0; j < 8; j++) { o0[j] = eh[j]; o1[j] = et[j]; }
    }

    // ---- A assignment: one row per thread, 4 k-quads per tile ----
    const int arow = tid & 127;                 // row within tile
    const int aq0  = tid >> 7;                  // 0..1; quads aq0+2j
    const int growA = i * NR + rowBase + arow;
    const float* Arow = g_v + (size_t)growA * LSEQ;

    // normalization scale for this row (deterministic fixed-order sum)
    float ssum = 0.f;
    #pragma unroll
    for (int c = 0; c < NLC; c++) ssum += g_spart[(size_t)growA * NLC + c];
    const float scl = 1.f / (ssum + 1e-5f);

    // B assignment (as before)
    const float* B = seq + (size_t)i * LSEQ * DMODEL;
    int bn[4], bk2[4];
    #pragma unroll
    for (int j = 0; j < 4; j++) {
        int p = tid + j * 256;
        bn[j]  = p & 63;
        bk2[j] = p >> 6;
    }

    float c[2][4][4];
    #pragma unroll
    for (int mt = 0; mt < 2; mt++)
        #pragma unroll
        for (int nt = 0; nt < 4; nt++)
            #pragma unroll
            for (int r = 0; r < 4; r++) c[mt][nt][r] = 0.f;

    // ---- prologue loads (tile kk=0) ----
    float4 rA[4];
    float rB0[4], rB1[4];
    #pragma unroll
    for (int j = 0; j < 4; j++)
        rA[j] = *(const float4*)&Arow[(aq0 + 2 * j) * 4];
    #pragma unroll
    for (int j = 0; j < 4; j++) {
        const float* bp = &B[(size_t)(2 * bk2[j]) * DMODEL + colBase + bn[j]];
        rB0[j] = bp[0];
        rB1[j] = bp[DMODEL];
    }

    for (int kk = 0; kk < LSEQ; kk += BK) {
        // ---- store current regs to smem (scale + split + pack) ----
        #pragma unroll
        for (int j = 0; j < 4; j++) {
            int qj = aq0 + 2 * j;
            float f0 = rA[j].x * scl, f1 = rA[j].y * scl;
            float f2 = rA[j].z * scl, f3 = rA[j].w * scl;
            float h0, l0, h1, l1, h2, l2, h3, l3;
            bsplit(f0, h0, l0); bsplit(f1, h1, l1);
            bsplit(f2, h2, l2); bsplit(f3, h3, l3);
            uint2 phi = make_uint2(pack2(h0, h1), pack2(h2, h3));
            uint2 plo = make_uint2(pack2(l0, l1), pack2(l2, l3));
            *(uint2*)&As_hi[arow * AS_STRIDE + qj * 2] = phi;
            *(uint2*)&As_lo[arow * AS_STRIDE + qj * 2] = plo;
        }
        #pragma unroll
        for (int j = 0; j < 4; j++) {
            float h0, l0, h1, l1;
            bsplit(rB0[j], h0, l0);
            bsplit(rB1[j], h1, l1);
            Bs_hi[bn[j] * BS_STRIDE + bk2[j]] = pack2(h0, h1);
            Bs_lo[bn[j] * BS_STRIDE + bk2[j]] = pack2(l0, l1);
        }
        __syncthreads();

        // ---- prefetch next tile ----
        if (kk + BK < LSEQ) {
            #pragma unroll
            for (int j = 0; j < 4; j++)
                rA[j] = *(const float4*)&Arow[kk + BK + (aq0 + 2 * j) * 4];
            #pragma unroll
            for (int j = 0; j < 4; j++) {
                const float* bp = &B[(size_t)(kk + BK + 2 * bk2[j]) * DMODEL
                                     + colBase + bn[j]];
                rB0[j] = bp[0];
                rB1[j] = bp[DMODEL];
            }
        }

        // ---- compute: 2 k16 sub-steps ----
        #pragma unroll
        for (int ks = 0; ks < 2; ks++) {
            const int k2b = ks * 8;
            unsigned ah[2][4], al[2][4];
            #pragma unroll
            for (int mt = 0; mt < 2; mt++) {
                int r0 = (warp_m + mt * 16 + g) * AS_STRIDE + k2b + q;
                int r1 = r0 + 8 * AS_STRIDE;
                ah[mt][0] = As_hi[r0];     ah[mt][1] = As_hi[r1];
                ah[mt][2] = As_hi[r0 + 4]; ah[mt][3] = As_hi[r1 + 4];
                al[mt][0] = As_lo[r0];     al[mt][1] = As_lo[r1];
                al[mt][2] = As_lo[r0 + 4]; al[mt][3] = As_lo[r1 + 4];
            }
            unsigned bh[4][2], bl[4][2];
            #pragma unroll
            for (int nt = 0; nt < 4; nt++) {
                int rb = (warp_n + nt * 8 + g) * BS_STRIDE + k2b + q;
                bh[nt][0] = Bs_hi[rb]; bh[nt][1] = Bs_hi[rb + 4];
                bl[nt][0] = Bs_lo[rb]; bl[nt][1] = Bs_lo[rb + 4];
            }
            #pragma unroll
            for (int mt = 0; mt < 2; mt++)
                #pragma unroll
                for (int nt = 0; nt < 4; nt++) {
                    float* cc = c[mt][nt];
                    mma16816(cc[0], cc[1], cc[2], cc[3],
                             ah[mt][0], ah[mt][1], ah[mt][2], ah[mt][3],
                             bh[nt][0], bh[nt][1]);
                    mma16816(cc[0], cc[1], cc[2], cc[3],
                             ah[mt][0], ah[mt][1], ah[mt][2], ah[mt][3],
                             bl[nt][0], bl[nt][1]);
                    mma16816(cc[0], cc[1], cc[2], cc[3],
                             al[mt][0], al[mt][1], al[mt][2], al[mt][3],
                             bh[nt][0], bh[nt][1]);
                }
        }
        __syncthreads();
    }

    // ---- epilogue: rs block ----
    float* O = out + ((size_t)2 * N_DOCS * NR + (size_t)i * NR) * DMODEL;
    #pragma unroll
    for (int mt = 0; mt < 2; mt++) {
        int row0 = rowBase + warp_m + mt * 16 + g;
        #pragma unroll
        for (int nt = 0; nt < 4; nt++) {
            int col = colBase + warp_n + nt * 8 + 2 * q;
            float2 v0 = make_float2(c[mt][nt][0], c[mt][nt][1]);
            float2 v1 = make_float2(c[mt][nt][2], c[mt][nt][3]);
            *(float2*)&O[(size_t)row0 * DMODEL + col]       = v0;
            *(float2*)&O[(size_t)(row0 + 8) * DMODEL + col] = v1;
        }
    }
}

// ---------------------------------------------------------------------------
extern "C" void kernel_launch(void* const* d_in, const int* in_sizes, int n_in,
                              void* d_out, int out_size)
{
    const float* seq   = (const float*)d_in[0];   // (4,1024,768) f32
    const float* att   = (const float*)d_in[1];   // (4,12,1024,1024) f32
    const int*   mpos  = (const int*)  d_in[2];   // (4,32,4) i32
    const float* mmask = (const float*)d_in[3];   // (4,32,4) f32
    const int*   hts   = (const int*)  d_in[4];   // (4,256,2) i32
    float* out = (float*)d_out;                   // (3, 4*256, 768) f32

    k_prep<<<N_DOCS * NE * NHP + N_DOCS * NE, 256>>>(seq, att, mpos, mmask);
    k_htA <<<dim3(NLC, N_DOCS, 2), 256>>>(hts);
    k_gemm<<<dim3(DMODEL / BN, NR / BM, N_DOCS), 256>>>(seq, hts, out);
}

// round 9
// speedup vs baseline: 1.3011x; 1.3011x over previous
#include <cuda_runtime.h>
#include <cuda_bf16.h>
#include <cstdint>

// Fixed shapes for HRTExtractor_81320910782627
#define N_DOCS 4
#define LSEQ   1024
#define DMODEL 768
#define NHEAD  12
#define NE     32
#define NM     4
#define NR     256
#define POS_OFFSET 1
#define NEG_INF (-3.402823466e38f)

#define LC   32
#define NLC  (LSEQ / LC)      // 32

// Scratch (device globals; allocation forbidden)
__device__ float g_eemb[N_DOCS * NE * DMODEL];            // (i,e,d)
__device__ float g_eatt[N_DOCS * NE * NHEAD * LSEQ];      // (i,e,h,l)
__device__ float g_v   [N_DOCS * NR * LSEQ];              // unnormalized ht_att
__device__ float g_spart[N_DOCS * NR * NLC];              // per-chunk partial sums

// ---------------------------------------------------------------------------
__device__ __forceinline__ void bsplit(float x, float& hi, float& lo) {
    __nv_bfloat16 h = __float2bfloat16(x);
    float hf = __bfloat162float(h);
    hi = hf;
    lo = x - hf;
}
__device__ __forceinline__ unsigned pack2(float a, float b) {
    __nv_bfloat162 v = __floats2bfloat162_rn(a, b);
    return *reinterpret_cast<unsigned*>(&v);
}

// ---------------------------------------------------------------------------
// Kernel 1 (fused): blocks [0, 4*32*3) -> e_att (4 heads/block, MLP=16),
//                   blocks [.., +128)  -> e_emb (logsumexp)
// ---------------------------------------------------------------------------
#define NHG (NHEAD / 4)   // 3 head-groups of 4

__global__ __launch_bounds__(256) void k_prep(
    const float* __restrict__ seq,      // (n, L, d)
    const float* __restrict__ att,      // (n, h, L, L)
    const int*   __restrict__ mpos,     // (n, E, M)
    const float* __restrict__ mmask)    // (n, E, M)
{
    if (blockIdx.x < N_DOCS * NE * NHG) {
        int b  = blockIdx.x;
        int hg = b % NHG;
        int ie = b / NHG;
        int i  = ie / NE;
        int h0 = hg * 4;

        int   p[NM];
        float mk[NM];
        float cnt = 0.f;
        #pragma unroll
        for (int m = 0; m < NM; m++) {
            p[m]  = mpos[ie * NM + m] + POS_OFFSET;
            mk[m] = mmask[ie * NM + m];
            cnt += mk[m];
        }
        float inv = 1.f / fmaxf(cnt, 1.f);

        int l4 = threadIdx.x * 4;
        float4 a[4];
        #pragma unroll
        for (int hh = 0; hh < 4; hh++) a[hh] = make_float4(0.f, 0.f, 0.f, 0.f);

        #pragma unroll
        for (int m = 0; m < NM; m++) {
            #pragma unroll
            for (int hh = 0; hh < 4; hh++) {
                const float4 x = *(const float4*)&att[
                    (((size_t)i * NHEAD + h0 + hh) * LSEQ + p[m]) * LSEQ + l4];
                a[hh].x += mk[m] * x.x; a[hh].y += mk[m] * x.y;
                a[hh].z += mk[m] * x.z; a[hh].w += mk[m] * x.w;
            }
        }
        #pragma unroll
        for (int hh = 0; hh < 4; hh++) {
            float4 o = make_float4(a[hh].x * inv, a[hh].y * inv,
                                   a[hh].z * inv, a[hh].w * inv);
            *(float4*)&g_eatt[((size_t)ie * NHEAD + h0 + hh) * LSEQ + l4] = o;
        }
    } else {
        int ie = blockIdx.x - N_DOCS * NE * NHG;
        int i  = ie / NE;

        __shared__ int   sp[NM];
        __shared__ float sm[NM];
        if (threadIdx.x < NM) {
            sp[threadIdx.x] = mpos[ie * NM + threadIdx.x] + POS_OFFSET;
            sm[threadIdx.x] = mmask[ie * NM + threadIdx.x];
        }
        __syncthreads();

        for (int dd = threadIdx.x; dd < DMODEL; dd += blockDim.x) {
            float v[NM];
            float mx = NEG_INF;
            #pragma unroll
            for (int m = 0; m < NM; m++) {
                float x = (sm[m] > 0.f)
                    ? seq[((size_t)i * LSEQ + sp[m]) * DMODEL + dd]
                    : NEG_INF;
                v[m] = x;
                mx = fmaxf(mx, x);
            }
            float s = 0.f;
            #pragma unroll
            for (int m = 0; m < NM; m++) s += expf(v[m] - mx);
            g_eemb[(size_t)ie * DMODEL + dd] = logf(s) + mx;
        }
    }
}

// ---------------------------------------------------------------------------
// Kernel 2: k_htA — smem-tiled pairwise head dot (unchanged from r8; correct).
// ---------------------------------------------------------------------------
__global__ __launch_bounds__(256) void k_htA(const int* __restrict__ hts)
{
    __shared__ __align__(16) float sA[NHEAD][NE][LC];   // 48 KB

    const int lc = blockIdx.x;
    const int i  = blockIdx.y;
    const int rh = blockIdx.z;
    const int l0 = lc * LC;

    for (int idx = threadIdx.x; idx < NHEAD * NE * (LC / 4); idx += 256) {
        int q  = idx & (LC / 4 - 1);
        int eh = idx >> 3;
        int e  = eh & (NE - 1);
        int h  = eh >> 5;
        float4 v = *(const float4*)&g_eatt[
            ((size_t)(i * NE + e) * NHEAD + h) * LSEQ + l0 + q * 4];
        *(float4*)&sA[h][e][q * 4] = v;
    }
    __syncthreads();

    const int warp = threadIdx.x >> 5;
    const int lane = threadIdx.x & 31;
    const int rbase = rh * 128 + warp * 16;

    int2 ep = ((const int2*)hts)[i * NR + rbase + (lane & 15)];
    float* vout = g_v + ((size_t)i * NR + rbase) * LSEQ + l0;

    #pragma unroll 4
    for (int rr = 0; rr < 16; rr++) {
        int e0 = __shfl_sync(0xffffffffu, ep.x, rr);
        int e1 = __shfl_sync(0xffffffffu, ep.y, rr);
        float acc = 0.f;
        #pragma unroll
        for (int h = 0; h < NHEAD; h++)
            acc += sA[h][e0][lane] * sA[h][e1][lane];
        acc *= (1.f / NHEAD);
        vout[(size_t)rr * LSEQ + lane] = acc;

        float t = acc;
        #pragma unroll
        for (int o = 16; o; o >>= 1) t += __shfl_xor_sync(0xffffffffu, t, o);
        if (lane == 0)
            g_spart[(size_t)(i * NR + rbase + rr) * NLC + lc] = t;
    }
}

// ---------------------------------------------------------------------------
// Kernel 3: rs = ht @ seq via HMMA bf16 3-term split.
// A sourced from fp32 g_v with COALESCED tile loads (round-4 pattern);
// per-row normalization scale built once per block from g_spart (coalesced);
// scale+split+pack fused at the smem-store; hs/ts gather fused in prologue.
// Block 256 thr, BM=128 BN=64 BK=32, grid (12,2,4) = 96 blocks.
// ---------------------------------------------------------------------------
#define BM 128
#define BN 64
#define BK 32
#define AS_STRIDE 20
#define BS_STRIDE 20

__device__ __forceinline__ void mma16816(
    float& c0, float& c1, float& c2, float& c3,
    unsigned a0, unsigned a1, unsigned a2, unsigned a3,
    unsigned b0, unsigned b1)
{
    asm volatile(
        "mma.sync.aligned.m16n8k16.row.col.f32.bf16.bf16.f32 "
        "{%0,%1,%2,%3}, {%4,%5,%6,%7}, {%8,%9}, {%0,%1,%2,%3};\n"
        : "+f"(c0), "+f"(c1), "+f"(c2), "+f"(c3)
        : "r"(a0), "r"(a1), "r"(a2), "r"(a3), "r"(b0), "r"(b1));
}

__global__ __launch_bounds__(256) void k_gemm(
    const float* __restrict__ seq,      // (n, L, d)
    const int*   __restrict__ hts,
    float* __restrict__ out)
{
    __shared__ __align__(16) unsigned As_hi[BM * AS_STRIDE];
    __shared__ __align__(16) unsigned As_lo[BM * AS_STRIDE];
    __shared__ __align__(16) unsigned Bs_hi[BN * BS_STRIDE];
    __shared__ __align__(16) unsigned Bs_lo[BN * BS_STRIDE];
    __shared__ float s_scl[BM];
    __shared__ float s_tmp[256];

    const int i       = blockIdx.z;
    const int rowBase = blockIdx.y * BM;
    const int colBase = blockIdx.x * BN;

    const int tid  = threadIdx.x;
    const int wid  = tid >> 5;
    const int lane = tid & 31;
    const int g    = lane >> 2;
    const int q    = lane & 3;

    const int warp_m = (wid & 3) * 32;
    const int warp_n = (wid >> 2) * 32;

    // ---- per-row normalization scales from g_spart (coalesced) ----
    {
        const float* sp = g_spart + (size_t)(i * NR + rowBase) * NLC;
        // thread t sums floats [t*16, t*16+16) = half of row (t>>1)
        const float4* sp4 = (const float4*)(sp + tid * 16);
        float s = 0.f;
        #pragma unroll
        for (int j = 0; j < 4; j++) {
            float4 v = sp4[j];
            s += v.x + v.y + v.z + v.w;
        }
        s_tmp[tid] = s;
    }

    // ---- fused hs/ts gather for this (row,col) tile ----
    {
        int row  = tid >> 1;
        int half = tid & 1;
        int b = i * NR + rowBase + row;
        int e0 = hts[b * 2 + 0];
        int e1 = hts[b * 2 + 1];
        const float4* eh = (const float4*)&g_eemb[
            (size_t)(i * NE + e0) * DMODEL + colBase + half * 32];
        const float4* et = (const float4*)&g_eemb[
            (size_t)(i * NE + e1) * DMODEL + colBase + half * 32];
        float4* o0 = (float4*)&out[(size_t)b * DMODEL + colBase + half * 32];
        float4* o1 = (float4*)&out[
            ((size_t)N_DOCS * NR + b) * DMODEL + colBase + half * 32];
        #pragma unroll
        for (int j = 0; j < 8; j++) { o0[j] = eh[j]; o1[j] = et[j]; }
    }
    __syncthreads();
    if (tid < BM)
        s_scl[tid] = 1.f / (s_tmp[2 * tid] + s_tmp[2 * tid + 1] + 1e-5f);
    __syncthreads();

    // ---- A copy assignment: coalesced fp32 tiles from g_v ----
    // chunk c = tid + j*256 (c < 1024): row = c>>3, q4 = c&7 (float4 in row)
    const float* Av = g_v + (size_t)(i * NR + rowBase) * LSEQ;
    int arow[4], aq[4];
    #pragma unroll
    for (int j = 0; j < 4; j++) {
        int c = tid + j * 256;
        arow[j] = c >> 3;
        aq[j]   = c & 7;
    }

    // ---- B copy assignment (round-4 pattern) ----
    const float* B = seq + (size_t)i * LSEQ * DMODEL;
    int bn[4], bk2[4];
    #pragma unroll
    for (int j = 0; j < 4; j++) {
        int p = tid + j * 256;
        bn[j]  = p & 63;
        bk2[j] = p >> 6;
    }

    float c[2][4][4];
    #pragma unroll
    for (int mt = 0; mt < 2; mt++)
        #pragma unroll
        for (int nt = 0; nt < 4; nt++)
            #pragma unroll
            for (int r = 0; r < 4; r++) c[mt][nt][r] = 0.f;

    // ---- prologue loads (tile kk=0) ----
    float4 rA[4];
    float rB0[4], rB1[4];
    #pragma unroll
    for (int j = 0; j < 4; j++)
        rA[j] = *(const float4*)&Av[(size_t)arow[j] * LSEQ + aq[j] * 4];
    #pragma unroll
    for (int j = 0; j < 4; j++) {
        const float* bp = &B[(size_t)(2 * bk2[j]) * DMODEL + colBase + bn[j]];
        rB0[j] = bp[0];
        rB1[j] = bp[DMODEL];
    }

    for (int kk = 0; kk < LSEQ; kk += BK) {
        // ---- store current regs to smem (scale + split + pack) ----
        #pragma unroll
        for (int j = 0; j < 4; j++) {
            float scl = s_scl[arow[j]];
            float f0 = rA[j].x * scl, f1 = rA[j].y * scl;
            float f2 = rA[j].z * scl, f3 = rA[j].w * scl;
            float h0, l0, h1, l1, h2, l2, h3, l3;
            bsplit(f0, h0, l0); bsplit(f1, h1, l1);
            bsplit(f2, h2, l2); bsplit(f3, h3, l3);
            uint2 phi = make_uint2(pack2(h0, h1), pack2(h2, h3));
            uint2 plo = make_uint2(pack2(l0, l1), pack2(l2, l3));
            *(uint2*)&As_hi[arow[j] * AS_STRIDE + aq[j] * 2] = phi;
            *(uint2*)&As_lo[arow[j] * AS_STRIDE + aq[j] * 2] = plo;
        }
        #pragma unroll
        for (int j = 0; j < 4; j++) {
            float h0, l0, h1, l1;
            bsplit(rB0[j], h0, l0);
            bsplit(rB1[j], h1, l1);
            Bs_hi[bn[j] * BS_STRIDE + bk2[j]] = pack2(h0, h1);
            Bs_lo[bn[j] * BS_STRIDE + bk2[j]] = pack2(l0, l1);
        }
        __syncthreads();

        // ---- prefetch next tile ----
        if (kk + BK < LSEQ) {
            #pragma unroll
            for (int j = 0; j < 4; j++)
                rA[j] = *(const float4*)&Av[
                    (size_t)arow[j] * LSEQ + kk + BK + aq[j] * 4];
            #pragma unroll
            for (int j = 0; j < 4; j++) {
                const float* bp = &B[(size_t)(kk + BK + 2 * bk2[j]) * DMODEL
                                     + colBase + bn[j]];
                rB0[j] = bp[0];
                rB1[j] = bp[DMODEL];
            }
        }

        // ---- compute: 2 k16 sub-steps ----
        #pragma unroll
        for (int ks = 0; ks < 2; ks++) {
            const int k2b = ks * 8;
            unsigned ah[2][4], al[2][4];
            #pragma unroll
            for (int mt = 0; mt < 2; mt++) {
                int r0 = (warp_m + mt * 16 + g) * AS_STRIDE + k2b + q;
                int r1 = r0 + 8 * AS_STRIDE;
                ah[mt][0] = As_hi[r0];     ah[mt][1] = As_hi[r1];
                ah[mt][2] = As_hi[r0 + 4]; ah[mt][3] = As_hi[r1 + 4];
                al[mt][0] = As_lo[r0];     al[mt][1] = As_lo[r1];
                al[mt][2] = As_lo[r0 + 4]; al[mt][3] = As_lo[r1 + 4];
            }
            unsigned bh[4][2], bl[4][2];
            #pragma unroll
            for (int nt = 0; nt < 4; nt++) {
                int rb = (warp_n + nt * 8 + g) * BS_STRIDE + k2b + q;
                bh[nt][0] = Bs_hi[rb]; bh[nt][1] = Bs_hi[rb + 4];
                bl[nt][0] = Bs_lo[rb]; bl[nt][1] = Bs_lo[rb + 4];
            }
            #pragma unroll
            for (int mt = 0; mt < 2; mt++)
                #pragma unroll
                for (int nt = 0; nt < 4; nt++) {
                    float* cc = c[mt][nt];
                    mma16816(cc[0], cc[1], cc[2], cc[3],
                             ah[mt][0], ah[mt][1], ah[mt][2], ah[mt][3],
                             bh[nt][0], bh[nt][1]);
                    mma16816(cc[0], cc[1], cc[2], cc[3],
                             ah[mt][0], ah[mt][1], ah[mt][2], ah[mt][3],
                             bl[nt][0], bl[nt][1]);
                    mma16816(cc[0], cc[1], cc[2], cc[3],
                             al[mt][0], al[mt][1], al[mt][2], al[mt][3],
                             bh[nt][0], bh[nt][1]);
                }
        }
        __syncthreads();
    }

    // ---- epilogue: rs block ----
    float* O = out + ((size_t)2 * N_DOCS * NR + (size_t)i * NR) * DMODEL;
    #pragma unroll
    for (int mt = 0; mt < 2; mt++) {
        int row0 = rowBase + warp_m + mt * 16 + g;
        #pragma unroll
        for (int nt = 0; nt < 4; nt++) {
            int col = colBase + warp_n + nt * 8 + 2 * q;
            float2 v0 = make_float2(c[mt][nt][0], c[mt][nt][1]);
            float2 v1 = make_float2(c[mt][nt][2], c[mt][nt][3]);
            *(float2*)&O[(size_t)row0 * DMODEL + col]       = v0;
            *(float2*)&O[(size_t)(row0 + 8) * DMODEL + col] = v1;
        }
    }
}

// ---------------------------------------------------------------------------
extern "C" void kernel_launch(void* const* d_in, const int* in_sizes, int n_in,
                              void* d_out, int out_size)
{
    const float* seq   = (const float*)d_in[0];   // (4,1024,768) f32
    const float* att   = (const float*)d_in[1];   // (4,12,1024,1024) f32
    const int*   mpos  = (const int*)  d_in[2];   // (4,32,4) i32
    const float* mmask = (const float*)d_in[3];   // (4,32,4) f32
    const int*   hts   = (const int*)  d_in[4];   // (4,256,2) i32
    float* out = (float*)d_out;                   // (3, 4*256, 768) f32

    k_prep<<<N_DOCS * NE * NHG + N_DOCS * NE, 256>>>(seq, att, mpos, mmask);
    k_htA <<<dim3(NLC, N_DOCS, 2), 256>>>(hts);
    k_gemm<<<dim3(DMODEL / BN, NR / BM, N_DOCS), 256>>>(seq, hts, out);
}

// round 10
// speedup vs baseline: 1.4386x; 1.1057x over previous
#include <cuda_runtime.h>
#include <cuda_bf16.h>
#include <cstdint>

// Fixed shapes for HRTExtractor_81320910782627
#define N_DOCS 4
#define LSEQ   1024
#define DMODEL 768
#define NHEAD  12
#define NE     32
#define NM     4
#define NR     256
#define POS_OFFSET 1
#define NEG_INF (-3.402823466e38f)

#define LC   32
#define NLC  (LSEQ / LC)      // 32

// Scratch (device globals; allocation forbidden)
__device__ float    g_eemb[N_DOCS * NE * DMODEL];          // (i,e,d)
__device__ float    g_eatt[N_DOCS * NE * NHEAD * LSEQ];    // (i,e,h,l)
__device__ float    g_v   [N_DOCS * NR * LSEQ];            // unnormalized ht_att
__device__ float    g_spart[N_DOCS * NR * NLC];            // per-chunk partial sums
__device__ unsigned g_htp_hi[N_DOCS * NR * (LSEQ / 2)];    // packed bf16x2 hi
__device__ unsigned g_htp_lo[N_DOCS * NR * (LSEQ / 2)];    // packed bf16x2 lo

// ---------------------------------------------------------------------------
__device__ __forceinline__ void bsplit(float x, float& hi, float& lo) {
    __nv_bfloat16 h = __float2bfloat16(x);
    float hf = __bfloat162float(h);
    hi = hf;
    lo = x - hf;
}
__device__ __forceinline__ unsigned pack2(float a, float b) {
    __nv_bfloat162 v = __floats2bfloat162_rn(a, b);
    return *reinterpret_cast<unsigned*>(&v);
}

// ---------------------------------------------------------------------------
// Kernel 1 (fused): blocks [0, 4*32*6) -> e_att (2 heads/block, proven 9.8us),
//                   blocks [.., +128)  -> e_emb (logsumexp)
// ---------------------------------------------------------------------------
#define NHP (NHEAD / 2)   // 6 head-pairs

__global__ __launch_bounds__(256) void k_prep(
    const float* __restrict__ seq,      // (n, L, d)
    const float* __restrict__ att,      // (n, h, L, L)
    const int*   __restrict__ mpos,     // (n, E, M)
    const float* __restrict__ mmask)    // (n, E, M)
{
    if (blockIdx.x < N_DOCS * NE * NHP) {
        int b  = blockIdx.x;
        int hp = b % NHP;
        int ie = b / NHP;
        int i  = ie / NE;
        int h0 = hp * 2;

        int   p[NM];
        float mk[NM];
        float cnt = 0.f;
        #pragma unroll
        for (int m = 0; m < NM; m++) {
            p[m]  = mpos[ie * NM + m] + POS_OFFSET;
            mk[m] = mmask[ie * NM + m];
            cnt += mk[m];
        }
        float inv = 1.f / fmaxf(cnt, 1.f);

        int l4 = threadIdx.x * 4;
        float4 a0 = make_float4(0.f, 0.f, 0.f, 0.f);
        float4 a1 = make_float4(0.f, 0.f, 0.f, 0.f);
        #pragma unroll
        for (int m = 0; m < NM; m++) {
            const float4 x = *(const float4*)&att[
                (((size_t)i * NHEAD + h0)     * LSEQ + p[m]) * LSEQ + l4];
            const float4 y = *(const float4*)&att[
                (((size_t)i * NHEAD + h0 + 1) * LSEQ + p[m]) * LSEQ + l4];
            a0.x += mk[m] * x.x; a0.y += mk[m] * x.y;
            a0.z += mk[m] * x.z; a0.w += mk[m] * x.w;
            a1.x += mk[m] * y.x; a1.y += mk[m] * y.y;
            a1.z += mk[m] * y.z; a1.w += mk[m] * y.w;
        }
        float4 o0 = make_float4(a0.x * inv, a0.y * inv, a0.z * inv, a0.w * inv);
        float4 o1 = make_float4(a1.x * inv, a1.y * inv, a1.z * inv, a1.w * inv);
        *(float4*)&g_eatt[((size_t)ie * NHEAD + h0)     * LSEQ + l4] = o0;
        *(float4*)&g_eatt[((size_t)ie * NHEAD + h0 + 1) * LSEQ + l4] = o1;
    } else {
        int ie = blockIdx.x - N_DOCS * NE * NHP;
        int i  = ie / NE;

        __shared__ int   sp[NM];
        __shared__ float sm[NM];
        if (threadIdx.x < NM) {
            sp[threadIdx.x] = mpos[ie * NM + threadIdx.x] + POS_OFFSET;
            sm[threadIdx.x] = mmask[ie * NM + threadIdx.x];
        }
        __syncthreads();

        for (int dd = threadIdx.x; dd < DMODEL; dd += blockDim.x) {
            float v[NM];
            float mx = NEG_INF;
            #pragma unroll
            for (int m = 0; m < NM; m++) {
                float x = (sm[m] > 0.f)
                    ? seq[((size_t)i * LSEQ + sp[m]) * DMODEL + dd]
                    : NEG_INF;
                v[m] = x;
                mx = fmaxf(mx, x);
            }
            float s = 0.f;
            #pragma unroll
            for (int m = 0; m < NM; m++) s += expf(v[m] - mx);
            g_eemb[(size_t)ie * DMODEL + dd] = logf(s) + mx;
        }
    }
}

// ---------------------------------------------------------------------------
// Kernel 2: k_htA — smem-tiled pairwise head dot (measured-good).
// grid (NLC, N_DOCS, 2); block loads e_att[i,:,:,lchunk] (48KB) once.
// ---------------------------------------------------------------------------
__global__ __launch_bounds__(256) void k_htA(const int* __restrict__ hts)
{
    __shared__ __align__(16) float sA[NHEAD][NE][LC];   // 48 KB

    const int lc = blockIdx.x;
    const int i  = blockIdx.y;
    const int rh = blockIdx.z;
    const int l0 = lc * LC;

    for (int idx = threadIdx.x; idx < NHEAD * NE * (LC / 4); idx += 256) {
        int q  = idx & (LC / 4 - 1);
        int eh = idx >> 3;
        int e  = eh & (NE - 1);
        int h  = eh >> 5;
        float4 v = *(const float4*)&g_eatt[
            ((size_t)(i * NE + e) * NHEAD + h) * LSEQ + l0 + q * 4];
        *(float4*)&sA[h][e][q * 4] = v;
    }
    __syncthreads();

    const int warp = threadIdx.x >> 5;
    const int lane = threadIdx.x & 31;
    const int rbase = rh * 128 + warp * 16;

    int2 ep = ((const int2*)hts)[i * NR + rbase + (lane & 15)];
    float* vout = g_v + ((size_t)i * NR + rbase) * LSEQ + l0;

    #pragma unroll 4
    for (int rr = 0; rr < 16; rr++) {
        int e0 = __shfl_sync(0xffffffffu, ep.x, rr);
        int e1 = __shfl_sync(0xffffffffu, ep.y, rr);
        float acc = 0.f;
        #pragma unroll
        for (int h = 0; h < NHEAD; h++)
            acc += sA[h][e0][lane] * sA[h][e1][lane];
        acc *= (1.f / NHEAD);
        vout[(size_t)rr * LSEQ + lane] = acc;

        float t = acc;
        #pragma unroll
        for (int o = 16; o; o >>= 1) t += __shfl_xor_sync(0xffffffffu, t, o);
        if (lane == 0)
            g_spart[(size_t)(i * NR + rbase + rr) * NLC + lc] = t;
    }
}

// ---------------------------------------------------------------------------
// Kernel 3 (NEW, tiny): per pair-row b — finish normalization, bf16-split and
// pack into g_htp_hi/lo (r4 gemm's expected format), and copy hs/ts rows.
// grid: N_DOCS*NR = 1024 blocks, 256 threads. ~12 MB contiguous traffic.
// ---------------------------------------------------------------------------
__global__ __launch_bounds__(256) void k_pack(
    const int* __restrict__ hts,
    float* __restrict__ out)
{
    const int b = blockIdx.x;           // i*NR + r
    const int i = b / NR;

    __shared__ float s_scl;
    if (threadIdx.x < 32) {
        float v = g_spart[(size_t)b * NLC + threadIdx.x];
        #pragma unroll
        for (int o = 16; o; o >>= 1) v += __shfl_xor_sync(0xffffffffu, v, o);
        if (threadIdx.x == 0) s_scl = 1.f / (v + 1e-5f);
    }
    __syncthreads();
    const float scl = s_scl;

    // normalize + split + pack: thread t handles floats [4t, 4t+4)
    {
        float4 v = ((const float4*)(g_v + (size_t)b * LSEQ))[threadIdx.x];
        float f0 = v.x * scl, f1 = v.y * scl, f2 = v.z * scl, f3 = v.w * scl;
        float h0, l0, h1, l1, h2, l2, h3, l3;
        bsplit(f0, h0, l0); bsplit(f1, h1, l1);
        bsplit(f2, h2, l2); bsplit(f3, h3, l3);
        uint2 phi = make_uint2(pack2(h0, h1), pack2(h2, h3));
        uint2 plo = make_uint2(pack2(l0, l1), pack2(l2, l3));
        *(uint2*)&g_htp_hi[(size_t)b * (LSEQ / 2) + threadIdx.x * 2] = phi;
        *(uint2*)&g_htp_lo[(size_t)b * (LSEQ / 2) + threadIdx.x * 2] = plo;
    }

    // hs/ts copy: 768 floats = 192 float4 per row
    {
        int e0 = hts[b * 2 + 0];
        int e1 = hts[b * 2 + 1];
        const float4* eh = (const float4*)&g_eemb[(size_t)(i * NE + e0) * DMODEL];
        const float4* et = (const float4*)&g_eemb[(size_t)(i * NE + e1) * DMODEL];
        float4* o0 = (float4*)&out[(size_t)b * DMODEL];
        float4* o1 = (float4*)&out[((size_t)N_DOCS * NR + b) * DMODEL];
        if (threadIdx.x < 192) {
            o0[threadIdx.x] = eh[threadIdx.x];
            o1[threadIdx.x] = et[threadIdx.x];
        }
    }
}

// ---------------------------------------------------------------------------
// Kernel 4: rs = ht @ seq via HMMA bf16 3-term split.
// EXACT round-4 gemm (proven): reads g_htp_hi/lo, no extra work in mainloop.
// Block 256 thr, BM=128 BN=64 BK=32, grid (12,2,4) = 96 blocks.
// ---------------------------------------------------------------------------
#define BM 128
#define BN 64
#define BK 32
#define AS_STRIDE 20
#define BS_STRIDE 20

__device__ __forceinline__ void mma16816(
    float& c0, float& c1, float& c2, float& c3,
    unsigned a0, unsigned a1, unsigned a2, unsigned a3,
    unsigned b0, unsigned b1)
{
    asm volatile(
        "mma.sync.aligned.m16n8k16.row.col.f32.bf16.bf16.f32 "
        "{%0,%1,%2,%3}, {%4,%5,%6,%7}, {%8,%9}, {%0,%1,%2,%3};\n"
        : "+f"(c0), "+f"(c1), "+f"(c2), "+f"(c3)
        : "r"(a0), "r"(a1), "r"(a2), "r"(a3), "r"(b0), "r"(b1));
}

__global__ __launch_bounds__(256) void k_gemm(
    const float* __restrict__ seq,      // (n, L, d)
    float* __restrict__ out)
{
    __shared__ __align__(16) unsigned As_hi[BM * AS_STRIDE];
    __shared__ __align__(16) unsigned As_lo[BM * AS_STRIDE];
    __shared__ __align__(16) unsigned Bs_hi[BN * BS_STRIDE];
    __shared__ __align__(16) unsigned Bs_lo[BN * BS_STRIDE];

    const int i       = blockIdx.z;
    const int rowBase = blockIdx.y * BM;
    const int colBase = blockIdx.x * BN;

    const int tid  = threadIdx.x;
    const int wid  = tid >> 5;
    const int lane = tid & 31;
    const int g    = lane >> 2;
    const int q    = lane & 3;

    const int warp_m = (wid & 3) * 32;
    const int warp_n = (wid >> 2) * 32;

    const unsigned* Ah = g_htp_hi + ((size_t)(i * NR + rowBase)) * (LSEQ / 2);
    const unsigned* Al = g_htp_lo + ((size_t)(i * NR + rowBase)) * (LSEQ / 2);
    const float* B = seq + (size_t)i * LSEQ * DMODEL;

    const int ar0 = tid >> 2,          aq0 = (tid & 3) * 4;
    const int ar1 = (tid + 256) >> 2,  aq1 = aq0;
    int bn[4], bk2[4];
    #pragma unroll
    for (int j = 0; j < 4; j++) {
        int p = tid + j * 256;
        bn[j]  = p & 63;
        bk2[j] = p >> 6;
    }

    float c[2][4][4];
    #pragma unroll
    for (int mt = 0; mt < 2; mt++)
        #pragma unroll
        for (int nt = 0; nt < 4; nt++)
            #pragma unroll
            for (int r = 0; r < 4; r++) c[mt][nt][r] = 0.f;

    uint4 rAh0, rAh1, rAl0, rAl1;
    float rB0[4], rB1[4];
    {
        rAh0 = *(const uint4*)&Ah[ar0 * (LSEQ / 2) + aq0];
        rAh1 = *(const uint4*)&Ah[ar1 * (LSEQ / 2) + aq1];
        rAl0 = *(const uint4*)&Al[ar0 * (LSEQ / 2) + aq0];
        rAl1 = *(const uint4*)&Al[ar1 * (LSEQ / 2) + aq1];
        #pragma unroll
        for (int j = 0; j < 4; j++) {
            const float* bp = &B[(size_t)(2 * bk2[j]) * DMODEL + colBase + bn[j]];
            rB0[j] = bp[0];
            rB1[j] = bp[DMODEL];
        }
    }

    for (int kk = 0; kk < LSEQ; kk += BK) {
        *(uint4*)&As_hi[ar0 * AS_STRIDE + aq0] = rAh0;
        *(uint4*)&As_hi[ar1 * AS_STRIDE + aq1] = rAh1;
        *(uint4*)&As_lo[ar0 * AS_STRIDE + aq0] = rAl0;
        *(uint4*)&As_lo[ar1 * AS_STRIDE + aq1] = rAl1;
        #pragma unroll
        for (int j = 0; j < 4; j++) {
            float h0, l0, h1, l1;
            bsplit(rB0[j], h0, l0);
            bsplit(rB1[j], h1, l1);
            Bs_hi[bn[j] * BS_STRIDE + bk2[j]] = pack2(h0, h1);
            Bs_lo[bn[j] * BS_STRIDE + bk2[j]] = pack2(l0, l1);
        }
        __syncthreads();

        if (kk + BK < LSEQ) {
            const int kk2 = (kk + BK) >> 1;
            rAh0 = *(const uint4*)&Ah[ar0 * (LSEQ / 2) + kk2 + aq0];
            rAh1 = *(const uint4*)&Ah[ar1 * (LSEQ / 2) + kk2 + aq1];
            rAl0 = *(const uint4*)&Al[ar0 * (LSEQ / 2) + kk2 + aq0];
            rAl1 = *(const uint4*)&Al[ar1 * (LSEQ / 2) + kk2 + aq1];
            #pragma unroll
            for (int j = 0; j < 4; j++) {
                const float* bp = &B[(size_t)(kk + BK + 2 * bk2[j]) * DMODEL
                                     + colBase + bn[j]];
                rB0[j] = bp[0];
                rB1[j] = bp[DMODEL];
            }
        }

        #pragma unroll
        for (int ks = 0; ks < 2; ks++) {
            const int k2b = ks * 8;
            unsigned ah[2][4], al[2][4];
            #pragma unroll
            for (int mt = 0; mt < 2; mt++) {
                int r0 = (warp_m + mt * 16 + g) * AS_STRIDE + k2b + q;
                int r1 = r0 + 8 * AS_STRIDE;
                ah[mt][0] = As_hi[r0];     ah[mt][1] = As_hi[r1];
                ah[mt][2] = As_hi[r0 + 4]; ah[mt][3] = As_hi[r1 + 4];
                al[mt][0] = As_lo[r0];     al[mt][1] = As_lo[r1];
                al[mt][2] = As_lo[r0 + 4]; al[mt][3] = As_lo[r1 + 4];
            }
            unsigned bh[4][2], bl[4][2];
            #pragma unroll
            for (int nt = 0; nt < 4; nt++) {
                int rb = (warp_n + nt * 8 + g) * BS_STRIDE + k2b + q;
                bh[nt][0] = Bs_hi[rb]; bh[nt][1] = Bs_hi[rb + 4];
                bl[nt][0] = Bs_lo[rb]; bl[nt][1] = Bs_lo[rb + 4];
            }
            #pragma unroll
            for (int mt = 0; mt < 2; mt++)
                #pragma unroll
                for (int nt = 0; nt < 4; nt++) {
                    float* cc = c[mt][nt];
                    mma16816(cc[0], cc[1], cc[2], cc[3],
                             ah[mt][0], ah[mt][1], ah[mt][2], ah[mt][3],
                             bh[nt][0], bh[nt][1]);
                    mma16816(cc[0], cc[1], cc[2], cc[3],
                             ah[mt][0], ah[mt][1], ah[mt][2], ah[mt][3],
                             bl[nt][0], bl[nt][1]);
                    mma16816(cc[0], cc[1], cc[2], cc[3],
                             al[mt][0], al[mt][1], al[mt][2], al[mt][3],
                             bh[nt][0], bh[nt][1]);
                }
        }
        __syncthreads();
    }

    float* O = out + ((size_t)2 * N_DOCS * NR + (size_t)i * NR) * DMODEL;
    #pragma unroll
    for (int mt = 0; mt < 2; mt++) {
        int row0 = rowBase + warp_m + mt * 16 + g;
        #pragma unroll
        for (int nt = 0; nt < 4; nt++) {
            int col = colBase + warp_n + nt * 8 + 2 * q;
            float2 v0 = make_float2(c[mt][nt][0], c[mt][nt][1]);
            float2 v1 = make_float2(c[mt][nt][2], c[mt][nt][3]);
            *(float2*)&O[(size_t)row0 * DMODEL + col]       = v0;
            *(float2*)&O[(size_t)(row0 + 8) * DMODEL + col] = v1;
        }
    }
}

// ---------------------------------------------------------------------------
extern "C" void kernel_launch(void* const* d_in, const int* in_sizes, int n_in,
                              void* d_out, int out_size)
{
    const float* seq   = (const float*)d_in[0];   // (4,1024,768) f32
    const float* att   = (const float*)d_in[1];   // (4,12,1024,1024) f32
    const int*   mpos  = (const int*)  d_in[2];   // (4,32,4) i32
    const float* mmask = (const float*)d_in[3];   // (4,32,4) f32
    const int*   hts   = (const int*)  d_in[4];   // (4,256,2) i32
    float* out = (float*)d_out;                   // (3, 4*256, 768) f32

    k_prep<<<N_DOCS * NE * NHP + N_DOCS * NE, 256>>>(seq, att, mpos, mmask);
    k_htA <<<dim3(NLC, N_DOCS, 2), 256>>>(hts);
    k_pack<<<N_DOCS * NR, 256>>>(hts, out);
    k_gemm<<<dim3(DMODEL / BN, NR / BM, N_DOCS), 256>>>(seq, out);
}

// round 13
// speedup vs baseline: 1.5559x; 1.0815x over previous
#include <cuda_runtime.h>
#include <cuda_bf16.h>
#include <cstdint>

// Fixed shapes for HRTExtractor_81320910782627
#define N_DOCS 4
#define LSEQ   1024
#define DMODEL 768
#define NHEAD  12
#define NE     32
#define NM     4
#define NR     256
#define POS_OFFSET 1
#define NEG_INF (-3.402823466e38f)

#define LC   32
#define NLC  (LSEQ / LC)      // 32

// Scratch (device globals; allocation forbidden)
__device__ float    g_eemb[N_DOCS * NE * DMODEL];          // (i,e,d)
__device__ float    g_eatt[N_DOCS * NE * NHEAD * LSEQ];    // (i,e,h,l)
__device__ float    g_v   [N_DOCS * NR * LSEQ];            // unnormalized ht_att
__device__ float    g_spart[N_DOCS * NR * NLC];            // per-chunk partial sums
__device__ unsigned g_htp_hi[N_DOCS * NR * (LSEQ / 2)];    // packed bf16x2 hi
__device__ unsigned g_htp_lo[N_DOCS * NR * (LSEQ / 2)];    // packed bf16x2 lo

// ---------------------------------------------------------------------------
__device__ __forceinline__ void bsplit(float x, float& hi, float& lo) {
    __nv_bfloat16 h = __float2bfloat16(x);
    float hf = __bfloat162float(h);
    hi = hf;
    lo = x - hf;
}
__device__ __forceinline__ unsigned pack2(float a, float b) {
    __nv_bfloat162 v = __floats2bfloat162_rn(a, b);
    return *reinterpret_cast<unsigned*>(&v);
}

// ---------------------------------------------------------------------------
// Kernel 1 (fused): blocks [0, 4*32*6) -> e_att (2 heads/block),
//                   blocks [.., +128)  -> e_emb (logsumexp)
// ---------------------------------------------------------------------------
#define NHP (NHEAD / 2)   // 6 head-pairs

__global__ __launch_bounds__(256) void k_prep(
    const float* __restrict__ seq,      // (n, L, d)
    const float* __restrict__ att,      // (n, h, L, L)
    const int*   __restrict__ mpos,     // (n, E, M)
    const float* __restrict__ mmask)    // (n, E, M)
{
    if (blockIdx.x < N_DOCS * NE * NHP) {
        int b  = blockIdx.x;
        int hp = b % NHP;
        int ie = b / NHP;
        int i  = ie / NE;
        int h0 = hp * 2;

        int   p[NM];
        float mk[NM];
        float cnt = 0.f;
        #pragma unroll
        for (int m = 0; m < NM; m++) {
            p[m]  = mpos[ie * NM + m] + POS_OFFSET;
            mk[m] = mmask[ie * NM + m];
            cnt += mk[m];
        }
        float inv = 1.f / fmaxf(cnt, 1.f);

        int l4 = threadIdx.x * 4;
        float4 a0 = make_float4(0.f, 0.f, 0.f, 0.f);
        float4 a1 = make_float4(0.f, 0.f, 0.f, 0.f);
        #pragma unroll
        for (int m = 0; m < NM; m++) {
            const float4 x = *(const float4*)&att[
                (((size_t)i * NHEAD + h0)     * LSEQ + p[m]) * LSEQ + l4];
            const float4 y = *(const float4*)&att[
                (((size_t)i * NHEAD + h0 + 1) * LSEQ + p[m]) * LSEQ + l4];
            a0.x += mk[m] * x.x; a0.y += mk[m] * x.y;
            a0.z += mk[m] * x.z; a0.w += mk[m] * x.w;
            a1.x += mk[m] * y.x; a1.y += mk[m] * y.y;
            a1.z += mk[m] * y.z; a1.w += mk[m] * y.w;
        }
        float4 o0 = make_float4(a0.x * inv, a0.y * inv, a0.z * inv, a0.w * inv);
        float4 o1 = make_float4(a1.x * inv, a1.y * inv, a1.z * inv, a1.w * inv);
        *(float4*)&g_eatt[((size_t)ie * NHEAD + h0)     * LSEQ + l4] = o0;
        *(float4*)&g_eatt[((size_t)ie * NHEAD + h0 + 1) * LSEQ + l4] = o1;
    } else {
        int ie = blockIdx.x - N_DOCS * NE * NHP;
        int i  = ie / NE;

        __shared__ int   sp[NM];
        __shared__ float sm[NM];
        if (threadIdx.x < NM) {
            sp[threadIdx.x] = mpos[ie * NM + threadIdx.x] + POS_OFFSET;
            sm[threadIdx.x] = mmask[ie * NM + threadIdx.x];
        }
        __syncthreads();

        for (int dd = threadIdx.x; dd < DMODEL; dd += blockDim.x) {
            float v[NM];
            float mx = NEG_INF;
            #pragma unroll
            for (int m = 0; m < NM; m++) {
                float x = (sm[m] > 0.f)
                    ? seq[((size_t)i * LSEQ + sp[m]) * DMODEL + dd]
                    : NEG_INF;
                v[m] = x;
                mx = fmaxf(mx, x);
            }
            float s = 0.f;
            #pragma unroll
            for (int m = 0; m < NM; m++) s += expf(v[m] - mx);
            g_eemb[(size_t)ie * DMODEL + dd] = logf(s) + mx;
        }
    }
}

// ---------------------------------------------------------------------------
// Kernel 2: k_htA — smem-tiled pairwise head dot (unchanged, proven).
// ---------------------------------------------------------------------------
__global__ __launch_bounds__(256) void k_htA(const int* __restrict__ hts)
{
    __shared__ __align__(16) float sA[NHEAD][NE][LC];   // 48 KB

    const int lc = blockIdx.x;
    const int i  = blockIdx.y;
    const int rh = blockIdx.z;
    const int l0 = lc * LC;

    for (int idx = threadIdx.x; idx < NHEAD * NE * (LC / 4); idx += 256) {
        int q  = idx & (LC / 4 - 1);
        int eh = idx >> 3;
        int e  = eh & (NE - 1);
        int h  = eh >> 5;
        float4 v = *(const float4*)&g_eatt[
            ((size_t)(i * NE + e) * NHEAD + h) * LSEQ + l0 + q * 4];
        *(float4*)&sA[h][e][q * 4] = v;
    }
    __syncthreads();

    const int warp = threadIdx.x >> 5;
    const int lane = threadIdx.x & 31;
    const int rbase = rh * 128 + warp * 16;

    int2 ep = ((const int2*)hts)[i * NR + rbase + (lane & 15)];
    float* vout = g_v + ((size_t)i * NR + rbase) * LSEQ + l0;

    #pragma unroll 4
    for (int rr = 0; rr < 16; rr++) {
        int e0 = __shfl_sync(0xffffffffu, ep.x, rr);
        int e1 = __shfl_sync(0xffffffffu, ep.y, rr);
        float acc = 0.f;
        #pragma unroll
        for (int h = 0; h < NHEAD; h++)
            acc += sA[h][e0][lane] * sA[h][e1][lane];
        acc *= (1.f / NHEAD);
        vout[(size_t)rr * LSEQ + lane] = acc;

        float t = acc;
        #pragma unroll
        for (int o = 16; o; o >>= 1) t += __shfl_xor_sync(0xffffffffu, t, o);
        if (lane == 0)
            g_spart[(size_t)(i * NR + rbase + rr) * NLC + lc] = t;
    }
}

// ---------------------------------------------------------------------------
// Kernel 3: k_pack — normalize + bf16 split/pack + hs/ts copy (unchanged).
// ---------------------------------------------------------------------------
__global__ __launch_bounds__(256) void k_pack(
    const int* __restrict__ hts,
    float* __restrict__ out)
{
    const int b = blockIdx.x;           // i*NR + r
    const int i = b / NR;

    __shared__ float s_scl;
    if (threadIdx.x < 32) {
        float v = g_spart[(size_t)b * NLC + threadIdx.x];
        #pragma unroll
        for (int o = 16; o; o >>= 1) v += __shfl_xor_sync(0xffffffffu, v, o);
        if (threadIdx.x == 0) s_scl = 1.f / (v + 1e-5f);
    }
    __syncthreads();
    const float scl = s_scl;

    {
        float4 v = ((const float4*)(g_v + (size_t)b * LSEQ))[threadIdx.x];
        float f0 = v.x * scl, f1 = v.y * scl, f2 = v.z * scl, f3 = v.w * scl;
        float h0, l0, h1, l1, h2, l2, h3, l3;
        bsplit(f0, h0, l0); bsplit(f1, h1, l1);
        bsplit(f2, h2, l2); bsplit(f3, h3, l3);
        uint2 phi = make_uint2(pack2(h0, h1), pack2(h2, h3));
        uint2 plo = make_uint2(pack2(l0, l1), pack2(l2, l3));
        *(uint2*)&g_htp_hi[(size_t)b * (LSEQ / 2) + threadIdx.x * 2] = phi;
        *(uint2*)&g_htp_lo[(size_t)b * (LSEQ / 2) + threadIdx.x * 2] = plo;
    }

    {
        int e0 = hts[b * 2 + 0];
        int e1 = hts[b * 2 + 1];
        const float4* eh = (const float4*)&g_eemb[(size_t)(i * NE + e0) * DMODEL];
        const float4* et = (const float4*)&g_eemb[(size_t)(i * NE + e1) * DMODEL];
        float4* o0 = (float4*)&out[(size_t)b * DMODEL];
        float4* o1 = (float4*)&out[((size_t)N_DOCS * NR + b) * DMODEL];
        if (threadIdx.x < 192) {
            o0[threadIdx.x] = eh[threadIdx.x];
            o1[threadIdx.x] = et[threadIdx.x];
        }
    }
}

// ---------------------------------------------------------------------------
// Kernel 4: rs = ht @ seq via HMMA bf16 3-term split.
// r10 gemm with ONE change: fragment loads via ldmatrix.x4 (8 LDSM/iter
// instead of 64 scalar LDS). Layout stride 20 u32 is LDSM-conflict-free.
// ---------------------------------------------------------------------------
#define BM 128
#define BN 64
#define BK 32
#define AS_STRIDE 20
#define BS_STRIDE 20

__device__ __forceinline__ void mma16816(
    float& c0, float& c1, float& c2, float& c3,
    unsigned a0, unsigned a1, unsigned a2, unsigned a3,
    unsigned b0, unsigned b1)
{
    asm volatile(
        "mma.sync.aligned.m16n8k16.row.col.f32.bf16.bf16.f32 "
        "{%0,%1,%2,%3}, {%4,%5,%6,%7}, {%8,%9}, {%0,%1,%2,%3};\n"
        : "+f"(c0), "+f"(c1), "+f"(c2), "+f"(c3)
        : "r"(a0), "r"(a1), "r"(a2), "r"(a3), "r"(b0), "r"(b1));
}

__device__ __forceinline__ void ldsm4(
    unsigned& r0, unsigned& r1, unsigned& r2, unsigned& r3, unsigned addr)
{
    asm volatile(
        "ldmatrix.sync.aligned.m8n8.x4.shared.b16 {%0,%1,%2,%3}, [%4];\n"
        : "=r"(r0), "=r"(r1), "=r"(r2), "=r"(r3) : "r"(addr));
}

__global__ __launch_bounds__(256) void k_gemm(
    const float* __restrict__ seq,      // (n, L, d)
    float* __restrict__ out)
{
    __shared__ __align__(16) unsigned As_hi[BM * AS_STRIDE];
    __shared__ __align__(16) unsigned As_lo[BM * AS_STRIDE];
    __shared__ __align__(16) unsigned Bs_hi[BN * BS_STRIDE];
    __shared__ __align__(16) unsigned Bs_lo[BN * BS_STRIDE];

    const int i       = blockIdx.z;
    const int rowBase = blockIdx.y * BM;
    const int colBase = blockIdx.x * BN;

    const int tid  = threadIdx.x;
    const int wid  = tid >> 5;
    const int lane = tid & 31;
    const int g    = lane >> 2;
    const int q    = lane & 3;

    const int warp_m = (wid & 3) * 32;
    const int warp_n = (wid >> 2) * 32;

    const unsigned* Ah = g_htp_hi + ((size_t)(i * NR + rowBase)) * (LSEQ / 2);
    const unsigned* Al = g_htp_lo + ((size_t)(i * NR + rowBase)) * (LSEQ / 2);
    const float* B = seq + (size_t)i * LSEQ * DMODEL;

    const int ar0 = tid >> 2,          aq0 = (tid & 3) * 4;
    const int ar1 = (tid + 256) >> 2,  aq1 = aq0;
    int bn[4], bk2[4];
    #pragma unroll
    for (int j = 0; j < 4; j++) {
        int p = tid + j * 256;
        bn[j]  = p & 63;
        bk2[j] = p >> 6;
    }

    // ---- ldmatrix lane addresses (loop-invariant; bytes) ----
    // A x4: m0=rows0-7/kp+0..3, m1=rows8-15/kp, m2=rows0-7/kp+4, m3=rows8-15/kp+4
    //   lane row_off = lane & 15, kp_off = (lane>>4)*4
    // B x4: m0=n0-7/kp, m1=n0-7/kp+4, m2=n8-15/kp, m3=n8-15/kp+4
    //   lane row_off = (lane&7) | ((lane>>1)&8), kp_off = ((lane>>3)&1)*4
    const int a_row = warp_m + (lane & 15);
    const int a_kp  = (lane >> 4) * 4;
    const int b_row = warp_n + ((lane & 7) | ((lane >> 1) & 8));
    const int b_kp  = ((lane >> 3) & 1) * 4;

    unsigned baseAh = (unsigned)__cvta_generic_to_shared(As_hi);
    unsigned baseAl = (unsigned)__cvta_generic_to_shared(As_lo);
    unsigned baseBh = (unsigned)__cvta_generic_to_shared(Bs_hi);
    unsigned baseBl = (unsigned)__cvta_generic_to_shared(Bs_lo);

    unsigned aAh[2], aAl[2], aBh[2], aBl[2];
    #pragma unroll
    for (int mt = 0; mt < 2; mt++) {
        unsigned off = ((a_row + mt * 16) * AS_STRIDE + a_kp) * 4u;
        aAh[mt] = baseAh + off;
        aAl[mt] = baseAl + off;
    }
    #pragma unroll
    for (int nt2 = 0; nt2 < 2; nt2++) {
        unsigned off = ((b_row + nt2 * 16) * BS_STRIDE + b_kp) * 4u;
        aBh[nt2] = baseBh + off;
        aBl[nt2] = baseBl + off;
    }

    float c[2][4][4];
    #pragma unroll
    for (int mt = 0; mt < 2; mt++)
        #pragma unroll
        for (int nt = 0; nt < 4; nt++)
            #pragma unroll
            for (int r = 0; r < 4; r++) c[mt][nt][r] = 0.f;

    uint4 rAh0, rAh1, rAl0, rAl1;
    float rB0[4], rB1[4];
    {
        rAh0 = *(const uint4*)&Ah[ar0 * (LSEQ / 2) + aq0];
        rAh1 = *(const uint4*)&Ah[ar1 * (LSEQ / 2) + aq1];
        rAl0 = *(const uint4*)&Al[ar0 * (LSEQ / 2) + aq0];
        rAl1 = *(const uint4*)&Al[ar1 * (LSEQ / 2) + aq1];
        #pragma unroll
        for (int j = 0; j < 4; j++) {
            const float* bp = &B[(size_t)(2 * bk2[j]) * DMODEL + colBase + bn[j]];
            rB0[j] = bp[0];
            rB1[j] = bp[DMODEL];
        }
    }

    for (int kk = 0; kk < LSEQ; kk += BK) {
        *(uint4*)&As_hi[ar0 * AS_STRIDE + aq0] = rAh0;
        *(uint4*)&As_hi[ar1 * AS_STRIDE + aq1] = rAh1;
        *(uint4*)&As_lo[ar0 * AS_STRIDE + aq0] = rAl0;
        *(uint4*)&As_lo[ar1 * AS_STRIDE + aq1] = rAl1;
        #pragma unroll
        for (int j = 0; j < 4; j++) {
            float h0, l0, h1, l1;
            bsplit(rB0[j], h0, l0);
            bsplit(rB1[j], h1, l1);
            Bs_hi[bn[j] * BS_STRIDE + bk2[j]] = pack2(h0, h1);
            Bs_lo[bn[j] * BS_STRIDE + bk2[j]] = pack2(l0, l1);
        }
        __syncthreads();

        if (kk + BK < LSEQ) {
            const int kk2 = (kk + BK) >> 1;
            rAh0 = *(const uint4*)&Ah[ar0 * (LSEQ / 2) + kk2 + aq0];
            rAh1 = *(const uint4*)&Ah[ar1 * (LSEQ / 2) + kk2 + aq1];
            rAl0 = *(const uint4*)&Al[ar0 * (LSEQ / 2) + kk2 + aq0];
            rAl1 = *(const uint4*)&Al[ar1 * (LSEQ / 2) + kk2 + aq1];
            #pragma unroll
            for (int j = 0; j < 4; j++) {
                const float* bp = &B[(size_t)(kk + BK + 2 * bk2[j]) * DMODEL
                                     + colBase + bn[j]];
                rB0[j] = bp[0];
                rB1[j] = bp[DMODEL];
            }
        }

        #pragma unroll
        for (int ks = 0; ks < 2; ks++) {
            const unsigned ko = ks * 8 * 4u;   // k2b=8 u32 -> 32 bytes
            unsigned ah[2][4], al[2][4];
            #pragma unroll
            for (int mt = 0; mt < 2; mt++) {
                ldsm4(ah[mt][0], ah[mt][1], ah[mt][2], ah[mt][3], aAh[mt] + ko);
                ldsm4(al[mt][0], al[mt][1], al[mt][2], al[mt][3], aAl[mt] + ko);
            }
            unsigned bh[4][2], bl[4][2];
            #pragma unroll
            for (int nt2 = 0; nt2 < 2; nt2++) {
                ldsm4(bh[nt2 * 2][0], bh[nt2 * 2][1],
                      bh[nt2 * 2 + 1][0], bh[nt2 * 2 + 1][1], aBh[nt2] + ko);
                ldsm4(bl[nt2 * 2][0], bl[nt2 * 2][1],
                      bl[nt2 * 2 + 1][0], bl[nt2 * 2 + 1][1], aBl[nt2] + ko);
            }
            #pragma unroll
            for (int mt = 0; mt < 2; mt++)
                #pragma unroll
                for (int nt = 0; nt < 4; nt++) {
                    float* cc = c[mt][nt];
                    mma16816(cc[0], cc[1], cc[2], cc[3],
                             ah[mt][0], ah[mt][1], ah[mt][2], ah[mt][3],
                             bh[nt][0], bh[nt][1]);
                    mma16816(cc[0], cc[1], cc[2], cc[3],
                             ah[mt][0], ah[mt][1], ah[mt][2], ah[mt][3],
                             bl[nt][0], bl[nt][1]);
                    mma16816(cc[0], cc[1], cc[2], cc[3],
                             al[mt][0], al[mt][1], al[mt][2], al[mt][3],
                             bh[nt][0], bh[nt][1]);
                }
        }
        __syncthreads();
    }

    float* O = out + ((size_t)2 * N_DOCS * NR + (size_t)i * NR) * DMODEL;
    #pragma unroll
    for (int mt = 0; mt < 2; mt++) {
        int row0 = rowBase + warp_m + mt * 16 + g;
        #pragma unroll
        for (int nt = 0; nt < 4; nt++) {
            int col = colBase + warp_n + nt * 8 + 2 * q;
            float2 v0 = make_float2(c[mt][nt][0], c[mt][nt][1]);
            float2 v1 = make_float2(c[mt][nt][2], c[mt][nt][3]);
            *(float2*)&O[(size_t)row0 * DMODEL + col]       = v0;
            *(float2*)&O[(size_t)(row0 + 8) * DMODEL + col] = v1;
        }
    }
}

// ---------------------------------------------------------------------------
extern "C" void kernel_launch(void* const* d_in, const int* in_sizes, int n_in,
                              void* d_out, int out_size)
{
    const float* seq   = (const float*)d_in[0];   // (4,1024,768) f32
    const float* att   = (const float*)d_in[1];   // (4,12,1024,1024) f32
    const int*   mpos  = (const int*)  d_in[2];   // (4,32,4) i32
    const float* mmask = (const float*)d_in[3];   // (4,32,4) f32
    const int*   hts   = (const int*)  d_in[4];   // (4,256,2) i32
    float* out = (float*)d_out;                   // (3, 4*256, 768) f32

    k_prep<<<N_DOCS * NE * NHP + N_DOCS * NE, 256>>>(seq, att, mpos, mmask);
    k_htA <<<dim3(NLC, N_DOCS, 2), 256>>>(hts);
    k_pack<<<N_DOCS * NR, 256>>>(hts, out);
    k_gemm<<<dim3(DMODEL / BN, NR / BM, N_DOCS), 256>>>(seq, out);
}